// round 15
// baseline (speedup 1.0000x reference)
#include <cuda_runtime.h>

typedef unsigned long long u64;

#define POS_DIM 15
#define N_LAYERS 32
#define H 16
#define IN_DIM (4 + 4 * 2 * POS_DIM)   // 124
#define THREADS 256
#define ROWS 2

#define W1_N (IN_DIM * H)        // 1984 floats
#define WS_N (N_LAYERS * H * H)  // 8192 floats
#define BS_N (N_LAYERS * H)      // 512 floats

// ---- weights in the constant bank (42.6KB < 64KB) ----
// Declared as vector types so loads are LDC.128/LDC.64 with zero repacking.
__constant__ ulonglong2 cWs[WS_N / 4];   // 32KB: [L][k][q] -> L*64 + k*4 + q
__constant__ ulonglong2 cW1[W1_N / 4];   // 7.75KB: [feat][q] -> feat*4 + q
__constant__ u64        cBs[BS_N / 2];   // 2KB: [L][jp] -> L*8 + jp
__constant__ u64        cB1[H / 2];
__constant__ float      cWf[H];
__constant__ float      cBf[1];

// ---- packed f32x2 helpers ----
__device__ __forceinline__ u64 pack2(float lo, float hi) {
    u64 r; asm("mov.b64 %0, {%1, %2};" : "=l"(r) : "f"(lo), "f"(hi)); return r;
}
__device__ __forceinline__ void unpack2(u64 v, float& lo, float& hi) {
    asm("mov.b64 {%0, %1}, %2;" : "=f"(lo), "=f"(hi) : "l"(v));
}
__device__ __forceinline__ u64 fma2(u64 a, u64 b, u64 c) {
    u64 d; asm("fma.rn.f32x2 %0, %1, %2, %3;" : "=l"(d) : "l"(a), "l"(b), "l"(c)); return d;
}
__device__ __forceinline__ u64 mul2(u64 a, u64 b) {
    u64 d; asm("mul.rn.f32x2 %0, %1, %2;" : "=l"(d) : "l"(a), "l"(b)); return d;
}
__device__ __forceinline__ u64 abs2(u64 a) { return a & 0x7fffffff7fffffffULL; }

// leaky(x) = 0.6x + 0.4|x|  (exact for slope 0.2)
#define C06 0x3F19999A3F19999AULL
#define C04 0x3ECCCCCD3ECCCCCDULL

__device__ __forceinline__ u64 resleaky2(u64 t, u64 h_old) {
    return fma2(abs2(t), C04, fma2(t, C06, h_old));
}
__device__ __forceinline__ u64 leaky2(u64 t) {
    return fma2(abs2(t), C04, mul2(t, C06));
}

__global__ __launch_bounds__(THREADS, 2)
void fractal_mlp_kernel(const float* __restrict__ z,
                        const float* __restrict__ c,
                        float* __restrict__ out,
                        int B)
{
    const int tid = threadIdx.x;
    const int base = blockIdx.x * (THREADS * ROWS) + tid;
    const int rowA = base;
    const int rowB = base + THREADS;
    const int rA = rowA < B ? rowA : B - 1;
    const int rB = rowB < B ? rowB : B - 1;

    const float2* z2 = reinterpret_cast<const float2*>(z);
    const float2* c2 = reinterpret_cast<const float2*>(c);
    float2 zA = z2[rA], cA = c2[rA];
    float2 zB = z2[rB], cB = c2[rB];
    float xA[4] = {zA.x, zA.y, cA.x, cA.y};
    float xB[4] = {zB.x, zB.y, cB.x, cB.y};

    // ---- First layer: acc = b1 + encoded(x) @ W1 (packed over output j pairs) ----
    u64 accA[8], accB[8];
#pragma unroll
    for (int p = 0; p < 8; p++) {
        u64 t = cB1[p];
        accA[p] = t; accB[p] = t;
    }

#define ACC2(feat, vA, vB)                                            \
    {                                                                 \
        const u64 pA = pack2((vA), (vA));                             \
        const u64 pB = pack2((vB), (vB));                             \
        _Pragma("unroll")                                             \
        for (int q = 0; q < 4; q++) {                                 \
            ulonglong2 wv = cW1[(feat) * 4 + q];                      \
            accA[2 * q]     = fma2(pA, wv.x, accA[2 * q]);            \
            accA[2 * q + 1] = fma2(pA, wv.y, accA[2 * q + 1]);        \
            accB[2 * q]     = fma2(pB, wv.x, accB[2 * q]);            \
            accB[2 * q + 1] = fma2(pB, wv.y, accB[2 * q + 1]);        \
        }                                                             \
    }

#pragma unroll
    for (int d = 0; d < 4; d++) ACC2(d, xA[d], xB[d]);

    // positional encoding: anchored double-angle (anchors f=0,5,10; 4 doublings each)
#pragma unroll 1
    for (int d = 0; d < 4; d++) {
        const float aAv = xA[d];
        const float aBv = xB[d];
#pragma unroll
        for (int an = 0; an < 3; an++) {
            const float sc = (an == 0) ? 1.0f : ((an == 1) ? 32.0f : 1024.0f);
            float sA, cAv, sB, cBv;
            sincosf(aAv * sc, &sA, &cAv);
            sincosf(aBv * sc, &sB, &cBv);
#pragma unroll
            for (int g = 0; g < 5; g++) {
                const int f = an * 5 + g;
                ACC2(4 + f * 8 + d, sA, sB);       // sin feature
                ACC2(8 + f * 8 + d, cAv, cBv);     // cos feature
                if (g < 4) {
                    float tA = sA * cAv;
                    float nA = fmaf(cAv, cAv, -(sA * sA));
                    sA = tA + tA; cAv = nA;
                    float tB = sB * cBv;
                    float nB = fmaf(cBv, cBv, -(sB * sB));
                    sB = tB + tB; cBv = nB;
                }
            }
        }
    }

    // first-layer leaky -> scalar h (scalars feed the per-k splats)
    float hA[H], hB[H];
#pragma unroll
    for (int p = 0; p < 8; p++) {
        unpack2(leaky2(accA[p]), hA[2 * p], hA[2 * p + 1]);
        unpack2(leaky2(accB[p]), hB[2 * p], hB[2 * p + 1]);
    }

    // ---- 32 residual layers: h += leaky(h @ W + b) ----
#pragma unroll 2
    for (int L = 0; L < N_LAYERS; L++) {
        u64 aA[8], aB[8];
#pragma unroll
        for (int p = 0; p < 8; p++) {
            u64 t = cBs[L * 8 + p];
            aA[p] = t; aB[p] = t;
        }
#pragma unroll
        for (int k = 0; k < H; k++) {
            const u64 vA = pack2(hA[k], hA[k]);
            const u64 vB = pack2(hB[k], hB[k]);
#pragma unroll
            for (int q = 0; q < 4; q++) {
                ulonglong2 wv = cWs[L * 64 + k * 4 + q];
                aA[2 * q]     = fma2(vA, wv.x, aA[2 * q]);
                aA[2 * q + 1] = fma2(vA, wv.y, aA[2 * q + 1]);
                aB[2 * q]     = fma2(vB, wv.x, aB[2 * q]);
                aB[2 * q + 1] = fma2(vB, wv.y, aB[2 * q + 1]);
            }
        }
        // fused residual+leaky: h' = h + 0.6t + 0.4|t|
#pragma unroll
        for (int p = 0; p < 8; p++) {
            u64 hpA = pack2(hA[2 * p], hA[2 * p + 1]);
            unpack2(resleaky2(aA[p], hpA), hA[2 * p], hA[2 * p + 1]);
            u64 hpB = pack2(hB[2 * p], hB[2 * p + 1]);
            unpack2(resleaky2(aB[p], hpB), hB[2 * p], hB[2 * p + 1]);
        }
    }

    // ---- Final: out = h @ Wf + bf ----
    float oA = cBf[0], oB = cBf[0];
#pragma unroll
    for (int j = 0; j < H; j++) {
        oA = fmaf(hA[j], cWf[j], oA);
        oB = fmaf(hB[j], cWf[j], oB);
    }
    if (rowA < B) out[rowA] = oA;
    if (rowB < B) out[rowB] = oB;
}

extern "C" void kernel_launch(void* const* d_in, const int* in_sizes, int n_in,
                              void* d_out, int out_size)
{
    const float* z  = (const float*)d_in[0];
    const float* c  = (const float*)d_in[1];
    const float* W1 = (const float*)d_in[2];
    const float* b1 = (const float*)d_in[3];
    const float* Ws = (const float*)d_in[4];
    const float* bs = (const float*)d_in[5];
    const float* Wf = (const float*)d_in[6];
    const float* bf = (const float*)d_in[7];

    // Stage weights into the constant bank (D2D async on default stream:
    // graph-capturable memcpy nodes, re-executed every replay — deterministic).
    cudaMemcpyToSymbolAsync(cWs, Ws, WS_N * sizeof(float), 0,
                            cudaMemcpyDeviceToDevice, 0);
    cudaMemcpyToSymbolAsync(cW1, W1, W1_N * sizeof(float), 0,
                            cudaMemcpyDeviceToDevice, 0);
    cudaMemcpyToSymbolAsync(cBs, bs, BS_N * sizeof(float), 0,
                            cudaMemcpyDeviceToDevice, 0);
    cudaMemcpyToSymbolAsync(cB1, b1, H * sizeof(float), 0,
                            cudaMemcpyDeviceToDevice, 0);
    cudaMemcpyToSymbolAsync(cWf, Wf, H * sizeof(float), 0,
                            cudaMemcpyDeviceToDevice, 0);
    cudaMemcpyToSymbolAsync(cBf, bf, sizeof(float), 0,
                            cudaMemcpyDeviceToDevice, 0);

    const int B = in_sizes[0] / 2;   // z is (B, 2)
    const int rows_per_block = THREADS * ROWS;
    const int blocks = (B + rows_per_block - 1) / rows_per_block;

    fractal_mlp_kernel<<<blocks, THREADS>>>(z, c, (float*)d_out, B);
}

// round 16
// speedup vs baseline: 2.7440x; 2.7440x over previous
#include <cuda_runtime.h>

typedef unsigned long long u64;

#define POS_DIM 15
#define N_LAYERS 32
#define H 16
#define IN_DIM (4 + 4 * 2 * POS_DIM)   // 124
#define THREADS 256
#define ROWS 2

#define W1_N (IN_DIM * H)        // 1984
#define WS_N (N_LAYERS * H * H)  // 8192
#define BS_N (N_LAYERS * H)      // 512

// ---- packed f32x2 helpers ----
__device__ __forceinline__ u64 pack2(float lo, float hi) {
    u64 r; asm("mov.b64 %0, {%1, %2};" : "=l"(r) : "f"(lo), "f"(hi)); return r;
}
__device__ __forceinline__ void unpack2(u64 v, float& lo, float& hi) {
    asm("mov.b64 {%0, %1}, %2;" : "=f"(lo), "=f"(hi) : "l"(v));
}
__device__ __forceinline__ u64 fma2(u64 a, u64 b, u64 c) {
    u64 d; asm("fma.rn.f32x2 %0, %1, %2, %3;" : "=l"(d) : "l"(a), "l"(b), "l"(c)); return d;
}
__device__ __forceinline__ u64 mul2(u64 a, u64 b) {
    u64 d; asm("mul.rn.f32x2 %0, %1, %2;" : "=l"(d) : "l"(a), "l"(b)); return d;
}
__device__ __forceinline__ u64 abs2(u64 a) { return a & 0x7fffffff7fffffffULL; }

// leaky(x) = 0.6x + 0.4|x|  (exact for slope 0.2)
#define C06 0x3F19999A3F19999AULL
#define C04 0x3ECCCCCD3ECCCCCDULL

__device__ __forceinline__ u64 resleaky2(u64 t, u64 h_old) {
    return fma2(abs2(t), C04, fma2(t, C06, h_old));
}
__device__ __forceinline__ u64 leaky2(u64 t) {
    return fma2(abs2(t), C04, mul2(t, C06));
}

__global__ __launch_bounds__(THREADS, 2)
void fractal_mlp_kernel(const float* __restrict__ z,
                        const float* __restrict__ c,
                        const float* __restrict__ W1,
                        const float* __restrict__ b1,
                        const float* __restrict__ Ws,
                        const float* __restrict__ bs,
                        const float* __restrict__ Wf,
                        const float* __restrict__ bf,
                        float* __restrict__ out,
                        int B)
{
    __shared__ __align__(16) float sW1[W1_N];
    __shared__ __align__(16) float sWs[WS_N];
    __shared__ __align__(16) float sBs[BS_N];
    __shared__ __align__(16) float sB1[H];
    __shared__ __align__(16) float sWf[H];
    __shared__ float sBf;

    const int tid = threadIdx.x;
    {   // vectorized staging
        const float4* g; float4* s;
        g = (const float4*)W1; s = (float4*)sW1;
        for (int i = tid; i < W1_N / 4; i += THREADS) s[i] = g[i];
        g = (const float4*)Ws; s = (float4*)sWs;
        for (int i = tid; i < WS_N / 4; i += THREADS) s[i] = g[i];
        g = (const float4*)bs; s = (float4*)sBs;
        for (int i = tid; i < BS_N / 4; i += THREADS) s[i] = g[i];
        if (tid < H) { sB1[tid] = b1[tid]; sWf[tid] = Wf[tid]; }
        if (tid == 0) sBf = bf[0];
    }
    __syncthreads();

    const int base = blockIdx.x * (THREADS * ROWS) + tid;
    const int rowA = base;
    const int rowB = base + THREADS;
    const int rA = rowA < B ? rowA : B - 1;
    const int rB = rowB < B ? rowB : B - 1;

    const float2* z2 = reinterpret_cast<const float2*>(z);
    const float2* c2 = reinterpret_cast<const float2*>(c);
    float2 zA = z2[rA], cA = c2[rA];
    float2 zB = z2[rB], cB = c2[rB];
    float xA[4] = {zA.x, zA.y, cA.x, cA.y};
    float xB[4] = {zB.x, zB.y, cB.x, cB.y};

    // ---- First layer: acc = b1 + encoded(x) @ W1 (packed over output j pairs) ----
    u64 accA[8], accB[8];
    {
        const ulonglong2* b1v = reinterpret_cast<const ulonglong2*>(sB1);
#pragma unroll
        for (int q = 0; q < 4; q++) {
            ulonglong2 t = b1v[q];
            accA[2 * q] = t.x; accA[2 * q + 1] = t.y;
            accB[2 * q] = t.x; accB[2 * q + 1] = t.y;
        }
    }

    const ulonglong2* w1v = reinterpret_cast<const ulonglong2*>(sW1);

#define ACC2(feat, vA, vB)                                            \
    {                                                                 \
        const u64 pA = pack2((vA), (vA));                             \
        const u64 pB = pack2((vB), (vB));                             \
        const ulonglong2* r = w1v + (feat) * 4;                       \
        _Pragma("unroll")                                             \
        for (int q = 0; q < 4; q++) {                                 \
            ulonglong2 wv = r[q];                                     \
            accA[2 * q]     = fma2(pA, wv.x, accA[2 * q]);            \
            accA[2 * q + 1] = fma2(pA, wv.y, accA[2 * q + 1]);        \
            accB[2 * q]     = fma2(pB, wv.x, accB[2 * q]);            \
            accB[2 * q + 1] = fma2(pB, wv.y, accB[2 * q + 1]);        \
        }                                                             \
    }

#pragma unroll
    for (int d = 0; d < 4; d++) ACC2(d, xA[d], xB[d]);

    // positional encoding: anchored double-angle (anchors f=0,5,10; 4 doublings each)
#pragma unroll 1
    for (int d = 0; d < 4; d++) {
        const float aAv = xA[d];
        const float aBv = xB[d];
#pragma unroll
        for (int an = 0; an < 3; an++) {
            const float sc = (an == 0) ? 1.0f : ((an == 1) ? 32.0f : 1024.0f);
            float sA, cAv, sB, cBv;
            sincosf(aAv * sc, &sA, &cAv);
            sincosf(aBv * sc, &sB, &cBv);
#pragma unroll
            for (int g = 0; g < 5; g++) {
                const int f = an * 5 + g;
                ACC2(4 + f * 8 + d, sA, sB);       // sin feature
                ACC2(8 + f * 8 + d, cAv, cBv);     // cos feature
                if (g < 4) {
                    float tA = sA * cAv;
                    float nA = fmaf(cAv, cAv, -(sA * sA));
                    sA = tA + tA; cAv = nA;
                    float tB = sB * cBv;
                    float nB = fmaf(cBv, cBv, -(sB * sB));
                    sB = tB + tB; cBv = nB;
                }
            }
        }
    }

    // first-layer leaky -> scalar h (scalars feed the per-k splats)
    float hA[H], hB[H];
#pragma unroll
    for (int p = 0; p < 8; p++) {
        unpack2(leaky2(accA[p]), hA[2 * p], hA[2 * p + 1]);
        unpack2(leaky2(accB[p]), hB[2 * p], hB[2 * p + 1]);
    }

    // ---- 32 residual layers: software-pipelined k-loop ----
    // Weight double-buffer: k+1's 4 LDS.128 issue BEFORE k's fma block, so the
    // 29-cyc (queued) LDS latency hides behind 32 fma2 issues (~64 cyc).
#pragma unroll 1
    for (int L = 0; L < N_LAYERS; L++) {
        const ulonglong2* w = reinterpret_cast<const ulonglong2*>(sWs + L * H * H);
        const ulonglong2* bb = reinterpret_cast<const ulonglong2*>(sBs + L * H);
        u64 aA[8], aB[8];
#pragma unroll
        for (int q = 0; q < 4; q++) {
            ulonglong2 t = bb[q];
            aA[2 * q] = t.x; aA[2 * q + 1] = t.y;
            aB[2 * q] = t.x; aB[2 * q + 1] = t.y;
        }

        ulonglong2 wc0 = w[0], wc1 = w[1], wc2 = w[2], wc3 = w[3];
#pragma unroll
        for (int k = 0; k < H; k++) {
            ulonglong2 wn0, wn1, wn2, wn3;
            if (k < H - 1) {   // prefetch k+1 (dead code folded on last iter)
                const ulonglong2* wn = w + (k + 1) * 4;
                wn0 = wn[0]; wn1 = wn[1]; wn2 = wn[2]; wn3 = wn[3];
            }
            const u64 vA = pack2(hA[k], hA[k]);
            const u64 vB = pack2(hB[k], hB[k]);
            aA[0] = fma2(vA, wc0.x, aA[0]);  aA[1] = fma2(vA, wc0.y, aA[1]);
            aB[0] = fma2(vB, wc0.x, aB[0]);  aB[1] = fma2(vB, wc0.y, aB[1]);
            aA[2] = fma2(vA, wc1.x, aA[2]);  aA[3] = fma2(vA, wc1.y, aA[3]);
            aB[2] = fma2(vB, wc1.x, aB[2]);  aB[3] = fma2(vB, wc1.y, aB[3]);
            aA[4] = fma2(vA, wc2.x, aA[4]);  aA[5] = fma2(vA, wc2.y, aA[5]);
            aB[4] = fma2(vB, wc2.x, aB[4]);  aB[5] = fma2(vB, wc2.y, aB[5]);
            aA[6] = fma2(vA, wc3.x, aA[6]);  aA[7] = fma2(vA, wc3.y, aA[7]);
            aB[6] = fma2(vB, wc3.x, aB[6]);  aB[7] = fma2(vB, wc3.y, aB[7]);
            if (k < H - 1) { wc0 = wn0; wc1 = wn1; wc2 = wn2; wc3 = wn3; }
        }

        // fused residual+leaky: h' = h + 0.6t + 0.4|t|
#pragma unroll
        for (int p = 0; p < 8; p++) {
            u64 hpA = pack2(hA[2 * p], hA[2 * p + 1]);
            unpack2(resleaky2(aA[p], hpA), hA[2 * p], hA[2 * p + 1]);
            u64 hpB = pack2(hB[2 * p], hB[2 * p + 1]);
            unpack2(resleaky2(aB[p], hpB), hB[2 * p], hB[2 * p + 1]);
        }
    }

    // ---- Final: out = h @ Wf + bf ----
    float oA = sBf, oB = sBf;
#pragma unroll
    for (int j = 0; j < H; j++) {
        oA = fmaf(hA[j], sWf[j], oA);
        oB = fmaf(hB[j], sWf[j], oB);
    }
    if (rowA < B) out[rowA] = oA;
    if (rowB < B) out[rowB] = oB;
}

extern "C" void kernel_launch(void* const* d_in, const int* in_sizes, int n_in,
                              void* d_out, int out_size)
{
    const float* z  = (const float*)d_in[0];
    const float* c  = (const float*)d_in[1];
    const float* W1 = (const float*)d_in[2];
    const float* b1 = (const float*)d_in[3];
    const float* Ws = (const float*)d_in[4];
    const float* bs = (const float*)d_in[5];
    const float* Wf = (const float*)d_in[6];
    const float* bf = (const float*)d_in[7];

    const int B = in_sizes[0] / 2;   // z is (B, 2)
    const int rows_per_block = THREADS * ROWS;
    const int blocks = (B + rows_per_block - 1) / rows_per_block;

    fractal_mlp_kernel<<<blocks, THREADS>>>(z, c, W1, b1, Ws, bs, Wf, bf,
                                            (float*)d_out, B);
}